// round 7
// baseline (speedup 1.0000x reference)
#include <cuda_runtime.h>
#include <cstdint>

// ---------------- problem constants ----------------
#define IN_CH   512
#define HID     128
#define OUT_CH  128
#define MAXN    1000000
#define MAXSEG  50000

// ---------------- device scratch (static; no runtime alloc) ----------------
__device__ float    g_h[(size_t)MAXN * HID];      // 512 MB: silu(fc1) activations
__device__ float    g_a[MAXN];                    // attention logits
__device__ float    g_e[MAXN];                    // exp(a - segmax)
__device__ unsigned g_smax[MAXSEG];               // monotone-mapped segment max
__device__ float    g_denom[MAXSEG];              // segment exp-sums
__device__ float    g_pooled[(size_t)MAXSEG * HID];

// ---------------- f32x2 packed-FMA helpers (sm_100+) ----------------
__device__ __forceinline__ unsigned long long pk(float lo, float hi) {
    unsigned long long r;
    asm("mov.b64 %0, {%1, %2};" : "=l"(r) : "f"(lo), "f"(hi));
    return r;
}
__device__ __forceinline__ void unpk(unsigned long long v, float& lo, float& hi) {
    asm("mov.b64 {%0, %1}, %2;" : "=f"(lo), "=f"(hi) : "l"(v));
}
__device__ __forceinline__ void ffma2(unsigned long long& c, unsigned long long a,
                                      unsigned long long b) {
    asm("fma.rn.f32x2 %0, %1, %2, %0;" : "+l"(c) : "l"(a), "l"(b));
}

// monotone float<->uint mapping for atomicMax over signed floats
__device__ __forceinline__ unsigned mapf(float f) {
    unsigned b = __float_as_uint(f);
    return (b & 0x80000000u) ? ~b : (b | 0x80000000u);
}
__device__ __forceinline__ float unmapf(unsigned u) {
    return (u & 0x80000000u) ? __uint_as_float(u & 0x7FFFFFFFu)
                             : __uint_as_float(~u);
}

// ---------------- kernel 0: zero scratch ----------------
__global__ void k_init(int S) {
    int t = blockIdx.x * blockDim.x + threadIdx.x;
    int stride = gridDim.x * blockDim.x;
    for (int i = t; i < S; i += stride) { g_smax[i] = 0u; g_denom[i] = 0.0f; }
    int tot = S * HID;
    for (int i = t; i < tot; i += stride) g_pooled[i] = 0.0f;
}

// ---------------- kernel 1: h = silu(x@W1+b1), a = h@Wa+ba ----------------
// 128x128 block tile, BK=16, 256 threads, 8x8 microtile via fma.rn.f32x2.
__global__ void __launch_bounds__(256)
k_gemm1(const float* __restrict__ x, const float* __restrict__ W1,
        const float* __restrict__ b1, const float* __restrict__ Wa,
        const float* __restrict__ ba, int N) {
    __shared__ __align__(16) float Xs[16][132];   // [k][m], padded
    __shared__ __align__(16) float Ws[16][128];   // [k][n]
    __shared__ float s_a[128];

    int tid = threadIdx.x;
    int row0 = blockIdx.x * 128;
    int m_base = (tid >> 4) << 3;
    int n_base = (tid & 15) << 3;
    if (tid < 128) s_a[tid] = 0.0f;

    unsigned long long acc[8][4];
#pragma unroll
    for (int i = 0; i < 8; i++)
#pragma unroll
        for (int j = 0; j < 4; j++) acc[i][j] = 0ull;

#pragma unroll 1
    for (int t = 0; t < IN_CH / 16; ++t) {
        int kk = t * 16;
        // X tile: 128 rows x 16 k  (2 float4 per thread)
#pragma unroll
        for (int i = 0; i < 2; i++) {
            int id = tid + i * 256;
            int r = id >> 2, kq = id & 3;
            float4 v = make_float4(0.f, 0.f, 0.f, 0.f);
            if (row0 + r < N)
                v = *(const float4*)(x + (size_t)(row0 + r) * IN_CH + kk + kq * 4);
            Xs[kq * 4 + 0][r] = v.x; Xs[kq * 4 + 1][r] = v.y;
            Xs[kq * 4 + 2][r] = v.z; Xs[kq * 4 + 3][r] = v.w;
        }
        // W tile: 16 k x 128 n
#pragma unroll
        for (int i = 0; i < 2; i++) {
            int id = tid + i * 256;
            int kw = id >> 5, j4 = id & 31;
            *(float4*)&Ws[kw][j4 * 4] =
                *(const float4*)(W1 + (size_t)(kk + kw) * HID + j4 * 4);
        }
        __syncthreads();
#pragma unroll
        for (int k = 0; k < 16; k++) {
            float4 a0 = *(const float4*)&Xs[k][m_base];
            float4 a1 = *(const float4*)&Xs[k][m_base + 4];
            float4 w0 = *(const float4*)&Ws[k][n_base];
            float4 w1 = *(const float4*)&Ws[k][n_base + 4];
            unsigned long long bp[4] = {pk(w0.x, w0.y), pk(w0.z, w0.w),
                                        pk(w1.x, w1.y), pk(w1.z, w1.w)};
            float am[8] = {a0.x, a0.y, a0.z, a0.w, a1.x, a1.y, a1.z, a1.w};
#pragma unroll
            for (int mi = 0; mi < 8; mi++) {
                unsigned long long ad = pk(am[mi], am[mi]);
#pragma unroll
                for (int nj = 0; nj < 4; nj++) ffma2(acc[mi][nj], ad, bp[nj]);
            }
        }
        __syncthreads();
    }

    // epilogue: bias + silu, store h, reduce attention logit into smem
    float bb[8], wa[8];
#pragma unroll
    for (int u = 0; u < 8; u++) { bb[u] = b1[n_base + u]; wa[u] = Wa[n_base + u]; }
    float ba0 = ba[0];
#pragma unroll
    for (int mi = 0; mi < 8; mi++) {
        int row = row0 + m_base + mi;
        if (row < N) {
            float v[8], s[8];
#pragma unroll
            for (int nj = 0; nj < 4; nj++) {
                float lo, hi;
                unpk(acc[mi][nj], lo, hi);
                v[nj * 2] = lo + bb[nj * 2];
                v[nj * 2 + 1] = hi + bb[nj * 2 + 1];
            }
            float part = 0.0f;
#pragma unroll
            for (int u = 0; u < 8; u++) {
                float t0 = v[u];
                float sg = 1.0f / (1.0f + __expf(-t0));
                s[u] = t0 * sg;
                part += s[u] * wa[u];
            }
            float4* hp = (float4*)(g_h + (size_t)row * HID + n_base);
            hp[0] = make_float4(s[0], s[1], s[2], s[3]);
            hp[1] = make_float4(s[4], s[5], s[6], s[7]);
            atomicAdd(&s_a[m_base + mi], part);
        }
    }
    __syncthreads();
    if (tid < 128) {
        int row = row0 + tid;
        if (row < N) g_a[row] = s_a[tid] + ba0;
    }
}

// ---------------- kernel 2: segment max (chunked, run-aggregated) ----------------
#define CHUNK 16
__global__ void k_segmax(const int* __restrict__ idx, int N) {
    int t = blockIdx.x * blockDim.x + threadIdx.x;
    int start = t * CHUNK;
    if (start >= N) return;
    int end = min(start + CHUNK, N);
    int cur = idx[start];
    float mx = g_a[start];
    for (int i = start + 1; i < end; i++) {
        int s = idx[i];
        float v = g_a[i];
        if (s == cur) mx = fmaxf(mx, v);
        else { atomicMax(&g_smax[cur], mapf(mx)); cur = s; mx = v; }
    }
    atomicMax(&g_smax[cur], mapf(mx));
}

// ---------------- kernel 3: e = exp(a - segmax), denom = segsum(e) ----------------
__global__ void k_exp(const int* __restrict__ idx, int N) {
    int t = blockIdx.x * blockDim.x + threadIdx.x;
    int start = t * CHUNK;
    if (start >= N) return;
    int end = min(start + CHUNK, N);
    int cur = idx[start];
    float m = unmapf(g_smax[cur]);
    float ex = __expf(g_a[start] - m);
    g_e[start] = ex;
    float sum = ex;
    for (int i = start + 1; i < end; i++) {
        int s = idx[i];
        if (s != cur) {
            atomicAdd(&g_denom[cur], sum);
            cur = s; m = unmapf(g_smax[cur]); sum = 0.0f;
        }
        float e2 = __expf(g_a[i] - m);
        g_e[i] = e2;
        sum += e2;
    }
    atomicAdd(&g_denom[cur], sum);
}

// ---------------- kernel 4: pooled[seg] += (e/denom) * h  (sorted runs) ----------------
// 128 threads = 128 columns; block handles 256 consecutive rows; flush on seg change.
__global__ void __launch_bounds__(128)
k_pool(const int* __restrict__ idx, int N) {
    __shared__ int s_idx[256];
    __shared__ float s_w[256];
    int base = blockIdx.x * 256;
    int tid = threadIdx.x;
    for (int r = tid; r < 256; r += 128) {
        int row = base + r;
        if (row < N) {
            int sg = idx[row];
            s_idx[r] = sg;
            s_w[r] = g_e[row] / g_denom[sg];
        } else {
            s_idx[r] = -1;
        }
    }
    __syncthreads();

    int j = tid;
    float sum = 0.0f;
    int cur = s_idx[0];
#pragma unroll 1
    for (int rb = 0; rb < 256; rb += 8) {
        float hv[8];
#pragma unroll
        for (int u = 0; u < 8; u++)
            hv[u] = (s_idx[rb + u] >= 0)
                        ? g_h[(size_t)(base + rb + u) * HID + j] : 0.0f;
#pragma unroll
        for (int u = 0; u < 8; u++) {
            int sg = s_idx[rb + u];
            if (sg < 0) goto done;
            if (sg != cur) {
                atomicAdd(&g_pooled[(size_t)cur * HID + j], sum);
                sum = 0.0f; cur = sg;
            }
            sum += s_w[rb + u] * hv[u];
        }
    }
done:
    atomicAdd(&g_pooled[(size_t)cur * HID + j], sum);
}

// ---------------- kernel 5: out = pooled @ Wo + bo ----------------
// 64-row tile, 256 threads, 8x4 microtile; Wo stays hot in L1 (64KB).
__global__ void __launch_bounds__(256)
k_out(const float* __restrict__ Wo, const float* __restrict__ bo,
      float* __restrict__ out, int S) {
    __shared__ __align__(16) float Ps[64][HID];
    int tid = threadIdx.x;
    int row0 = blockIdx.x * 64;
#pragma unroll
    for (int i = 0; i < 8; i++) {
        int id = tid + i * 256;        // 2048 float4 over 64 x 32
        int r = id >> 5, c4 = id & 31;
        float4 v = make_float4(0.f, 0.f, 0.f, 0.f);
        if (row0 + r < S)
            v = *(const float4*)&g_pooled[(size_t)(row0 + r) * HID + c4 * 4];
        *(float4*)&Ps[r][c4 * 4] = v;
    }
    __syncthreads();

    int m_base = (tid >> 5) * 8;
    int n_base = (tid & 31) * 4;
    unsigned long long acc[8][2] = {};
#pragma unroll 4
    for (int k = 0; k < HID; k++) {
        float4 b = *(const float4*)&Wo[(size_t)k * OUT_CH + n_base];
        unsigned long long b0 = pk(b.x, b.y), b1p = pk(b.z, b.w);
#pragma unroll
        for (int mi = 0; mi < 8; mi++) {
            float av = Ps[m_base + mi][k];          // warp-broadcast
            unsigned long long ad = pk(av, av);
            ffma2(acc[mi][0], ad, b0);
            ffma2(acc[mi][1], ad, b1p);
        }
    }
    float c0 = bo[n_base], c1 = bo[n_base + 1], c2 = bo[n_base + 2], c3 = bo[n_base + 3];
#pragma unroll
    for (int mi = 0; mi < 8; mi++) {
        int row = row0 + m_base + mi;
        if (row < S) {
            float l0, h0, l1, h1;
            unpk(acc[mi][0], l0, h0);
            unpk(acc[mi][1], l1, h1);
            *(float4*)&out[(size_t)row * OUT_CH + n_base] =
                make_float4(l0 + c0, h0 + c1, l1 + c2, h1 + c3);
        }
    }
}

// ---------------- launch ----------------
extern "C" void kernel_launch(void* const* d_in, const int* in_sizes, int n_in,
                              void* d_out, int out_size) {
    const float* x     = (const float*)d_in[0];
    const int*   index = (const int*)d_in[1];
    // trailing weights are order-stable regardless of whether num_segments
    // appears as an input: W1, b1, Wa, ba, Wo, bo are always the last six.
    const float* W1 = (const float*)d_in[n_in - 6];
    const float* b1 = (const float*)d_in[n_in - 5];
    const float* Wa = (const float*)d_in[n_in - 4];
    const float* ba = (const float*)d_in[n_in - 3];
    const float* Wo = (const float*)d_in[n_in - 2];
    const float* bo = (const float*)d_in[n_in - 1];
    float* out = (float*)d_out;

    int N = in_sizes[0] / IN_CH;       // 1,000,000
    int S = out_size / OUT_CH;         // 50,000

    k_init<<<256, 256>>>(S);
    k_gemm1<<<(N + 127) / 128, 256>>>(x, W1, b1, Wa, ba, N);
    int ct = (N + CHUNK - 1) / CHUNK;
    k_segmax<<<(ct + 255) / 256, 256>>>(index, N);
    k_exp<<<(ct + 255) / 256, 256>>>(index, N);
    k_pool<<<(N + 255) / 256, 128>>>(index, N);
    k_out<<<(S + 63) / 64, 256>>>(Wo, bo, out, S);
}

// round 9
// speedup vs baseline: 1.4173x; 1.4173x over previous
#include <cuda_runtime.h>
#include <cuda_bf16.h>
#include <cstdint>

// ---------------- problem constants ----------------
#define IN_CH   512
#define HID     128
#define OUT_CH  128
#define MAXN    1000000
#define MAXSEG  50000
#define BK      64                 // K per chunk (bf16 elems)
#define NCHUNK  (IN_CH / BK)       // 8
#define TILE_M  128

// ---------------- device scratch ----------------
__device__ __align__(16) float g_h[(size_t)MAXN * HID];
__device__ float    g_a[MAXN];
__device__ float    g_e[MAXN];
__device__ unsigned g_smax[MAXSEG];
__device__ float    g_denom[MAXSEG];
__device__ __align__(16) float g_pooled[(size_t)MAXSEG * HID];
__device__ __align__(16) __nv_bfloat16 g_Wh[HID * IN_CH];   // W1^T hi, [n][k]
__device__ __align__(16) __nv_bfloat16 g_Wl[HID * IN_CH];   // W1^T lo

// ---------------- smem layout (bytes, dynamic) ----------------
// bf16 tiles use 144B row stride (72 bf16): conflict-free ldmatrix.
#define RS        144
#define OFF_XH    0                       // [128][72] bf16  (18432)
#define OFF_XL    18432                   // [128][72] bf16  (18432)
#define OFF_W     36864                   // 2 stages x (Wh 18432 + Wl 18432)
#define WSTG      36864
#define OFF_XF    (OFF_W + 2 * WSTG)      // 2 stages x fp32 staging [128][68w]
#define XFROW     272
#define XFSTG     (128 * XFROW)           // 34816
#define OFF_SA    (OFF_XF + 2 * XFSTG)    // 512 B
#define SMEM_TOT  (OFF_SA + 512)          // 180736

// ---------------- helpers ----------------
__device__ __forceinline__ uint32_t smem_u32(const void* p) {
    uint32_t a;
    asm("{ .reg .u64 t; cvta.to.shared.u64 t, %1; cvt.u32.u64 %0, t; }"
        : "=r"(a) : "l"(p));
    return a;
}
__device__ __forceinline__ void cp16(uint32_t dst, const void* src, uint32_t srcsize) {
    asm volatile("cp.async.cg.shared.global [%0], [%1], 16, %2;"
                 :: "r"(dst), "l"(src), "r"(srcsize) : "memory");
}
__device__ __forceinline__ void cp_commit() {
    asm volatile("cp.async.commit_group;" ::: "memory");
}
__device__ __forceinline__ void cp_wait1() {
    asm volatile("cp.async.wait_group 1;" ::: "memory");
}
__device__ __forceinline__ void cp_wait0() {
    asm volatile("cp.async.wait_group 0;" ::: "memory");
}
#define LDSM_X4(r0, r1, r2, r3, addr) \
    asm volatile("ldmatrix.sync.aligned.m8n8.x4.shared.b16 {%0,%1,%2,%3}, [%4];" \
                 : "=r"(r0), "=r"(r1), "=r"(r2), "=r"(r3) : "r"(addr))
#define MMA16816(c, a, b0, b1) \
    asm volatile("mma.sync.aligned.m16n8k16.row.col.f32.bf16.bf16.f32 " \
                 "{%0,%1,%2,%3}, {%4,%5,%6,%7}, {%8,%9}, {%0,%1,%2,%3};" \
                 : "+f"((c)[0]), "+f"((c)[1]), "+f"((c)[2]), "+f"((c)[3]) \
                 : "r"((a)[0]), "r"((a)[1]), "r"((a)[2]), "r"((a)[3]), \
                   "r"(b0), "r"(b1))

// f32x2 helpers (k_out)
__device__ __forceinline__ unsigned long long pk(float lo, float hi) {
    unsigned long long r;
    asm("mov.b64 %0, {%1, %2};" : "=l"(r) : "f"(lo), "f"(hi));
    return r;
}
__device__ __forceinline__ void unpk(unsigned long long v, float& lo, float& hi) {
    asm("mov.b64 {%0, %1}, %2;" : "=f"(lo), "=f"(hi) : "l"(v));
}
__device__ __forceinline__ void ffma2(unsigned long long& c, unsigned long long a,
                                      unsigned long long b) {
    asm("fma.rn.f32x2 %0, %1, %2, %0;" : "+l"(c) : "l"(a), "l"(b));
}
__device__ __forceinline__ unsigned mapf(float f) {
    unsigned b = __float_as_uint(f);
    return (b & 0x80000000u) ? ~b : (b | 0x80000000u);
}
__device__ __forceinline__ float unmapf(unsigned u) {
    return (u & 0x80000000u) ? __uint_as_float(u & 0x7FFFFFFFu)
                             : __uint_as_float(~u);
}

// ---------------- kernel: prep W (transpose + bf16 hi/lo split) ----------------
__global__ void k_prepw(const float* __restrict__ W1) {
    int t = blockIdx.x * blockDim.x + threadIdx.x;
    if (t >= IN_CH * HID) return;
    int k = t / HID, n = t % HID;
    float w = W1[t];
    __nv_bfloat16 hi = __float2bfloat16(w);
    float lo = w - __bfloat162float(hi);
    g_Wh[(size_t)n * IN_CH + k] = hi;
    g_Wl[(size_t)n * IN_CH + k] = __float2bfloat16(lo);
}

// ---------------- kernel: zero scratch ----------------
__global__ void k_init(int S) {
    int t = blockIdx.x * blockDim.x + threadIdx.x;
    int stride = gridDim.x * blockDim.x;
    for (int i = t; i < S; i += stride) { g_smax[i] = 0u; g_denom[i] = 0.0f; }
    int tot = S * HID;
    for (int i = t; i < tot; i += stride) g_pooled[i] = 0.0f;
}

// ---------------- GEMM1 via mma.sync bf16 3-term split ----------------
__global__ void __launch_bounds__(256, 1)
k_gemm1(const float* __restrict__ x, const float* __restrict__ b1,
        const float* __restrict__ Wa, const float* __restrict__ ba, int N) {
    extern __shared__ __align__(128) char smem[];
    uint32_t sb = smem_u32(smem);
    int tid = threadIdx.x, wid = tid >> 5, lane = tid & 31;
    int mw = wid & 3, nw = wid >> 2;
    long row0 = (long)blockIdx.x * TILE_M;

    float* s_a = (float*)(smem + OFF_SA);
    if (tid < 128) s_a[tid] = 0.0f;

    // per-thread cp.async address components
    int ldrow = tid >> 1, ldhalf = tid & 1;
    long xrow = row0 + ldrow;
    bool xok = xrow < N;
    const float* xsrc0 = x + xrow * (long)IN_CH + ldhalf * 32;
    uint32_t xdst0 = sb + OFF_XF + (uint32_t)ldrow * XFROW + ldhalf * 128;

    // W cp.async: 4x16B per matrix per thread
    int wr[4], wu[4];
#pragma unroll
    for (int j = 0; j < 4; j++) {
        int id = (tid << 2) | j;
        wr[j] = id >> 3;       // n row 0..127
        wu[j] = id & 7;        // 16B unit (8 bf16)
    }

    // issue chunk 0
    {
        int kk = 0;
#pragma unroll
        for (int i = 0; i < 8; i++)
            cp16(xdst0 + i * 16, xsrc0 + kk + i * 4, xok ? 16u : 0u);
        uint32_t wb = sb + OFF_W;
#pragma unroll
        for (int j = 0; j < 4; j++) {
            cp16(wb + (uint32_t)wr[j] * RS + wu[j] * 16,
                 g_Wh + (size_t)wr[j] * IN_CH + kk + wu[j] * 8, 16u);
            cp16(wb + 18432 + (uint32_t)wr[j] * RS + wu[j] * 16,
                 g_Wl + (size_t)wr[j] * IN_CH + kk + wu[j] * 8, 16u);
        }
        cp_commit();
    }

    // accumulators: c[mt][nt][4]
    float acc[2][8][4];
#pragma unroll
    for (int a = 0; a < 2; a++)
#pragma unroll
        for (int b = 0; b < 8; b++)
#pragma unroll
            for (int q = 0; q < 4; q++) acc[a][b][q] = 0.0f;

    // ldmatrix per-thread invariants
    uint32_t aRow = (uint32_t)(mw * 32 + (lane & 15));
    uint32_t aCol = (uint32_t)((lane >> 4) * 16);
    int g = lane >> 3;
    uint32_t bRowOff = (uint32_t)(((g >> 1) * 8) + (lane & 7));
    uint32_t bCol = (uint32_t)((g & 1) * 16);
    uint32_t aAddrH = sb + OFF_XH + aRow * RS + aCol;
    uint32_t aAddrL = sb + OFF_XL + aRow * RS + aCol;
    uint32_t bBase = (uint32_t)(nw * 64) + bRowOff;

#pragma unroll 1
    for (int c = 0; c < NCHUNK; ++c) {
        int st = c & 1;
        // issue chunk c+1 into other stage
        if (c + 1 < NCHUNK) {
            int kk = (c + 1) * BK;
            int st2 = (c + 1) & 1;
            uint32_t xd = xdst0 + st2 * XFSTG;
#pragma unroll
            for (int i = 0; i < 8; i++)
                cp16(xd + i * 16, xsrc0 + kk + i * 4, xok ? 16u : 0u);
            uint32_t wb = sb + OFF_W + st2 * WSTG;
#pragma unroll
            for (int j = 0; j < 4; j++) {
                cp16(wb + (uint32_t)wr[j] * RS + wu[j] * 16,
                     g_Wh + (size_t)wr[j] * IN_CH + kk + wu[j] * 8, 16u);
                cp16(wb + 18432 + (uint32_t)wr[j] * RS + wu[j] * 16,
                     g_Wl + (size_t)wr[j] * IN_CH + kk + wu[j] * 8, 16u);
            }
            cp_commit();
            cp_wait1();
        } else {
            cp_wait0();
        }
        __syncthreads();

        // convert fp32 staging -> bf16 hi/lo tiles
        {
            const char* xf = smem + OFF_XF + st * XFSTG + ldrow * XFROW + ldhalf * 128;
            char* th = smem + OFF_XH + ldrow * RS + ldhalf * 64;
            char* tl = smem + OFF_XL + ldrow * RS + ldhalf * 64;
#pragma unroll
            for (int i = 0; i < 8; i++) {
                float4 v = *(const float4*)(xf + i * 16);
                __nv_bfloat16 h0 = __float2bfloat16(v.x), h1 = __float2bfloat16(v.y),
                              h2 = __float2bfloat16(v.z), h3 = __float2bfloat16(v.w);
                __nv_bfloat162 hp0, hp1;
                hp0.x = h0; hp0.y = h1; hp1.x = h2; hp1.y = h3;
                __nv_bfloat162 lp0 = __floats2bfloat162_rn(
                    v.x - __bfloat162float(h0), v.y - __bfloat162float(h1));
                __nv_bfloat162 lp1 = __floats2bfloat162_rn(
                    v.z - __bfloat162float(h2), v.w - __bfloat162float(h3));
                uint2 hu, lu;
                hu.x = reinterpret_cast<uint32_t&>(hp0);
                hu.y = reinterpret_cast<uint32_t&>(hp1);
                lu.x = reinterpret_cast<uint32_t&>(lp0);
                lu.y = reinterpret_cast<uint32_t&>(lp1);
                *(uint2*)(th + i * 8) = hu;
                *(uint2*)(tl + i * 8) = lu;
            }
        }
        __syncthreads();

        uint32_t wBaseH = sb + OFF_W + st * WSTG;
        uint32_t wBaseL = wBaseH + 18432;
#pragma unroll
        for (int ks = 0; ks < 4; ks++) {
            uint32_t kb = ks * 32;
            uint32_t ah[2][4], al[2][4];
#pragma unroll
            for (int mt = 0; mt < 2; mt++) {
                LDSM_X4(ah[mt][0], ah[mt][1], ah[mt][2], ah[mt][3],
                        aAddrH + mt * 16 * RS + kb);
                LDSM_X4(al[mt][0], al[mt][1], al[mt][2], al[mt][3],
                        aAddrL + mt * 16 * RS + kb);
            }
#pragma unroll
            for (int p = 0; p < 4; p++) {
                uint32_t brow = (bBase + p * 16) * RS + bCol + kb;
                uint32_t bh0, bh1, bh2, bh3, bl0, bl1, bl2, bl3;
                LDSM_X4(bh0, bh1, bh2, bh3, wBaseH + brow);
                LDSM_X4(bl0, bl1, bl2, bl3, wBaseL + brow);
#pragma unroll
                for (int mt = 0; mt < 2; mt++) {
                    MMA16816(acc[mt][p * 2 + 0], ah[mt], bh0, bh1);
                    MMA16816(acc[mt][p * 2 + 1], ah[mt], bh2, bh3);
                    MMA16816(acc[mt][p * 2 + 0], ah[mt], bl0, bl1);
                    MMA16816(acc[mt][p * 2 + 1], ah[mt], bl2, bl3);
                    MMA16816(acc[mt][p * 2 + 0], al[mt], bh0, bh1);
                    MMA16816(acc[mt][p * 2 + 1], al[mt], bh2, bh3);
                }
            }
        }
        __syncthreads();
    }

    // ---- epilogue: bias + silu + logit + store h ----
    float2 b1v[8], wav[8];
#pragma unroll
    for (int nt = 0; nt < 8; nt++) {
        int cb = nw * 64 + nt * 8 + (lane & 3) * 2;
        b1v[nt] = *(const float2*)&b1[cb];
        wav[nt] = *(const float2*)&Wa[cb];
    }
    long r0g = row0 + mw * 32 + (lane >> 2);
#pragma unroll
    for (int mt = 0; mt < 2; mt++) {
#pragma unroll
        for (int rh = 0; rh < 2; rh++) {
            long grow = r0g + mt * 16 + rh * 8;
            float part = 0.0f;
            if (grow < N) {
                float* hrow = g_h + (size_t)grow * HID;
#pragma unroll
                for (int nt = 0; nt < 8; nt++) {
                    float v0 = acc[mt][nt][rh * 2 + 0] + b1v[nt].x;
                    float v1 = acc[mt][nt][rh * 2 + 1] + b1v[nt].y;
                    float s0 = v0 / (1.0f + __expf(-v0));
                    float s1 = v1 / (1.0f + __expf(-v1));
                    part += s0 * wav[nt].x + s1 * wav[nt].y;
                    int cb = nw * 64 + nt * 8 + (lane & 3) * 2;
                    *(float2*)(hrow + cb) = make_float2(s0, s1);
                }
            }
            part += __shfl_xor_sync(0xffffffffu, part, 1);
            part += __shfl_xor_sync(0xffffffffu, part, 2);
            if ((lane & 3) == 0 && grow < N)
                atomicAdd(&s_a[(int)(grow - row0)], part);
        }
    }
    __syncthreads();
    if (tid < 128) {
        long row = row0 + tid;
        if (row < N) g_a[row] = s_a[tid] + ba[0];
    }
}

// ---------------- kernel: segment max ----------------
#define CHUNK 16
__global__ void k_segmax(const int* __restrict__ idx, int N) {
    int t = blockIdx.x * blockDim.x + threadIdx.x;
    int start = t * CHUNK;
    if (start >= N) return;
    int end = min(start + CHUNK, N);
    int cur = idx[start];
    float mx = g_a[start];
    for (int i = start + 1; i < end; i++) {
        int s = idx[i];
        float v = g_a[i];
        if (s == cur) mx = fmaxf(mx, v);
        else { atomicMax(&g_smax[cur], mapf(mx)); cur = s; mx = v; }
    }
    atomicMax(&g_smax[cur], mapf(mx));
}

// ---------------- kernel: exp + denom ----------------
__global__ void k_exp(const int* __restrict__ idx, int N) {
    int t = blockIdx.x * blockDim.x + threadIdx.x;
    int start = t * CHUNK;
    if (start >= N) return;
    int end = min(start + CHUNK, N);
    int cur = idx[start];
    float m = unmapf(g_smax[cur]);
    float ex = __expf(g_a[start] - m);
    g_e[start] = ex;
    float sum = ex;
    for (int i = start + 1; i < end; i++) {
        int s = idx[i];
        if (s != cur) {
            atomicAdd(&g_denom[cur], sum);
            cur = s; m = unmapf(g_smax[cur]); sum = 0.0f;
        }
        float e2 = __expf(g_a[i] - m);
        g_e[i] = e2;
        sum += e2;
    }
    atomicAdd(&g_denom[cur], sum);
}

// ---------------- kernel: weighted pooling over sorted runs ----------------
__global__ void __launch_bounds__(128)
k_pool(const int* __restrict__ idx, int N) {
    __shared__ int s_idx[256];
    __shared__ float s_w[256];
    int base = blockIdx.x * 256;
    int tid = threadIdx.x;
    for (int r = tid; r < 256; r += 128) {
        int row = base + r;
        if (row < N) {
            int sg = idx[row];
            s_idx[r] = sg;
            s_w[r] = g_e[row] / g_denom[sg];
        } else {
            s_idx[r] = -1;
        }
    }
    __syncthreads();

    int j = tid;
    float sum = 0.0f;
    int cur = s_idx[0];
#pragma unroll 1
    for (int rb = 0; rb < 256; rb += 8) {
        float hv[8];
#pragma unroll
        for (int u = 0; u < 8; u++)
            hv[u] = (s_idx[rb + u] >= 0)
                        ? g_h[(size_t)(base + rb + u) * HID + j] : 0.0f;
#pragma unroll
        for (int u = 0; u < 8; u++) {
            int sg = s_idx[rb + u];
            if (sg < 0) goto done;
            if (sg != cur) {
                atomicAdd(&g_pooled[(size_t)cur * HID + j], sum);
                sum = 0.0f; cur = sg;
            }
            sum += s_w[rb + u] * hv[u];
        }
    }
done:
    atomicAdd(&g_pooled[(size_t)cur * HID + j], sum);
}

// ---------------- kernel: out = pooled @ Wo + bo ----------------
__global__ void __launch_bounds__(256)
k_out(const float* __restrict__ Wo, const float* __restrict__ bo,
      float* __restrict__ out, int S) {
    __shared__ __align__(16) float Ps[64][HID];
    int tid = threadIdx.x;
    int row0 = blockIdx.x * 64;
#pragma unroll
    for (int i = 0; i < 8; i++) {
        int id = tid + i * 256;
        int r = id >> 5, c4 = id & 31;
        float4 v = make_float4(0.f, 0.f, 0.f, 0.f);
        if (row0 + r < S)
            v = *(const float4*)&g_pooled[(size_t)(row0 + r) * HID + c4 * 4];
        *(float4*)&Ps[r][c4 * 4] = v;
    }
    __syncthreads();

    int m_base = (tid >> 5) * 8;
    int n_base = (tid & 31) * 4;
    unsigned long long acc[8][2] = {};
#pragma unroll 4
    for (int k = 0; k < HID; k++) {
        float4 b = *(const float4*)&Wo[(size_t)k * OUT_CH + n_base];
        unsigned long long b0 = pk(b.x, b.y), b1p = pk(b.z, b.w);
#pragma unroll
        for (int mi = 0; mi < 8; mi++) {
            float av = Ps[m_base + mi][k];
            unsigned long long ad = pk(av, av);
            ffma2(acc[mi][0], ad, b0);
            ffma2(acc[mi][1], ad, b1p);
        }
    }
    float c0 = bo[n_base], c1 = bo[n_base + 1], c2 = bo[n_base + 2], c3 = bo[n_base + 3];
#pragma unroll
    for (int mi = 0; mi < 8; mi++) {
        int row = row0 + m_base + mi;
        if (row < S) {
            float l0, h0, l1, h1;
            unpk(acc[mi][0], l0, h0);
            unpk(acc[mi][1], l1, h1);
            *(float4*)&out[(size_t)row * OUT_CH + n_base] =
                make_float4(l0 + c0, h0 + c1, l1 + c2, h1 + c3);
        }
    }
}

// ---------------- launch ----------------
extern "C" void kernel_launch(void* const* d_in, const int* in_sizes, int n_in,
                              void* d_out, int out_size) {
    const float* x     = (const float*)d_in[0];
    const int*   index = (const int*)d_in[1];
    const float* W1 = (const float*)d_in[n_in - 6];
    const float* b1 = (const float*)d_in[n_in - 5];
    const float* Wa = (const float*)d_in[n_in - 4];
    const float* ba = (const float*)d_in[n_in - 3];
    const float* Wo = (const float*)d_in[n_in - 2];
    const float* bo = (const float*)d_in[n_in - 1];
    float* out = (float*)d_out;

    int N = in_sizes[0] / IN_CH;       // 1,000,000
    int S = out_size / OUT_CH;         // 50,000

    static int attr_set = 0;
    if (!attr_set) {
        cudaFuncSetAttribute(k_gemm1, cudaFuncAttributeMaxDynamicSharedMemorySize,
                             SMEM_TOT);
        attr_set = 1;
    }

    k_prepw<<<(IN_CH * HID + 255) / 256, 256>>>(W1);
    k_init<<<256, 256>>>(S);
    k_gemm1<<<(N + TILE_M - 1) / TILE_M, 256, SMEM_TOT>>>(x, b1, Wa, ba, N);
    int ct = (N + CHUNK - 1) / CHUNK;
    k_segmax<<<(ct + 255) / 256, 256>>>(index, N);
    k_exp<<<(ct + 255) / 256, 256>>>(index, N);
    k_pool<<<(N + 255) / 256, 128>>>(index, N);
    k_out<<<(S + 63) / 64, 256>>>(Wo, bo, out, S);
}

// round 10
// speedup vs baseline: 1.6976x; 1.1978x over previous
#include <cuda_runtime.h>
#include <cuda_bf16.h>
#include <cstdint>

// ---------------- problem constants ----------------
#define IN_CH   512
#define HID     128
#define OUT_CH  128
#define MAXN    1000000
#define MAXSEG  50000
#define NT16    (IN_CH / 16)       // 32 k16-steps

// ---------------- device scratch ----------------
__device__ __align__(16) float g_h[(size_t)MAXN * HID];
__device__ float    g_a[MAXN];
__device__ float    g_e[MAXN];
__device__ unsigned g_smax[MAXSEG];
__device__ float    g_denom[MAXSEG];
__device__ __align__(16) float g_pooled[(size_t)MAXSEG * HID];
// W fragments in mma.sync B-operand register layout:
// index = ((t16 * 8) + n16blk) * 32 + lane, 16B each (regs b0,b1,b2,b3)
__device__ __align__(16) uint4 g_Wfh[NT16 * 8 * 32];
__device__ __align__(16) uint4 g_Wfl[NT16 * 8 * 32];

// ---------------- helpers ----------------
#define MMA16816(c, a0, a1, a2, a3, b0, b1) \
    asm volatile("mma.sync.aligned.m16n8k16.row.col.f32.bf16.bf16.f32 " \
                 "{%0,%1,%2,%3}, {%4,%5,%6,%7}, {%8,%9}, {%0,%1,%2,%3};" \
                 : "+f"((c)[0]), "+f"((c)[1]), "+f"((c)[2]), "+f"((c)[3]) \
                 : "r"(a0), "r"(a1), "r"(a2), "r"(a3), "r"(b0), "r"(b1))

__device__ __forceinline__ uint32_t bf2bits(__nv_bfloat162 v) {
    return *reinterpret_cast<uint32_t*>(&v);
}
// split a float2 into bf16x2 hi and bf16x2 lo (lo = exact residual, rounded)
__device__ __forceinline__ void split2(float2 v, uint32_t& h, uint32_t& l) {
    __nv_bfloat162 hb = __floats2bfloat162_rn(v.x, v.y);
    float2 hf = __bfloat1622float2(hb);
    __nv_bfloat162 lb = __floats2bfloat162_rn(v.x - hf.x, v.y - hf.y);
    h = bf2bits(hb);
    l = bf2bits(lb);
}
__device__ __forceinline__ uint32_t pkbf(float a, float b) {
    return bf2bits(__floats2bfloat162_rn(a, b));
}

// f32x2 helpers (k_out)
__device__ __forceinline__ unsigned long long pk(float lo, float hi) {
    unsigned long long r;
    asm("mov.b64 %0, {%1, %2};" : "=l"(r) : "f"(lo), "f"(hi));
    return r;
}
__device__ __forceinline__ void unpk(unsigned long long v, float& lo, float& hi) {
    asm("mov.b64 {%0, %1}, %2;" : "=f"(lo), "=f"(hi) : "l"(v));
}
__device__ __forceinline__ void ffma2(unsigned long long& c, unsigned long long a,
                                      unsigned long long b) {
    asm("fma.rn.f32x2 %0, %1, %2, %0;" : "+l"(c) : "l"(a), "l"(b));
}
__device__ __forceinline__ unsigned mapf(float f) {
    unsigned b = __float_as_uint(f);
    return (b & 0x80000000u) ? ~b : (b | 0x80000000u);
}
__device__ __forceinline__ float unmapf(unsigned u) {
    return (u & 0x80000000u) ? __uint_as_float(u & 0x7FFFFFFFu)
                             : __uint_as_float(~u);
}

// ---------------- kernel: build W fragment tables ----------------
// One thread per (t16, n16blk, lane) = 32*8*32 = 8192.
__global__ void k_prepw(const float* __restrict__ W1) {
    int t = blockIdx.x * blockDim.x + threadIdx.x;
    if (t >= NT16 * 8 * 32) return;
    int lane = t & 31;
    int p    = (t >> 5) & 7;       // n16 block
    int kt   = t >> 8;             // k16 step
    int tig = lane & 3, g = lane >> 2;
    int k0 = kt * 16 + tig * 2;
    int n0 = p * 16 + g;

    float wh[8], wl[8];
    // order: reg0 (k0,k0+1 | n0), reg1 (k0+8,k0+9 | n0),
    //        reg2 (k0,k0+1 | n0+8), reg3 (k0+8,k0+9 | n0+8)
#pragma unroll
    for (int r = 0; r < 4; r++) {
        int k = k0 + (r & 1) * 8;
        int n = n0 + (r >> 1) * 8;
#pragma unroll
        for (int e = 0; e < 2; e++) {
            float w = W1[(size_t)(k + e) * HID + n];
            __nv_bfloat16 hb = __float2bfloat16(w);
            float hf = __bfloat162float(hb);
            wh[r * 2 + e] = hf;
            wl[r * 2 + e] = w - hf;
        }
    }
    size_t base = ((size_t)kt * 8 + p) * 32 + lane;
    uint4 H, L;
    H.x = pkbf(wh[0], wh[1]); H.y = pkbf(wh[2], wh[3]);
    H.z = pkbf(wh[4], wh[5]); H.w = pkbf(wh[6], wh[7]);
    L.x = pkbf(wl[0], wl[1]); L.y = pkbf(wl[2], wl[3]);
    L.z = pkbf(wl[4], wl[5]); L.w = pkbf(wl[6], wl[7]);
    g_Wfh[base] = H;
    g_Wfl[base] = L;
}

// ---------------- kernel: zero scratch ----------------
__global__ void k_init(int S) {
    int t = blockIdx.x * blockDim.x + threadIdx.x;
    int stride = gridDim.x * blockDim.x;
    for (int i = t; i < S; i += stride) { g_smax[i] = 0u; g_denom[i] = 0.0f; }
    int tot = S * HID;
    for (int i = t; i < tot; i += stride) g_pooled[i] = 0.0f;
}

// ---------------- GEMM1: register-fragment mma.sync, no smem mainloop -------
// CTA = 256 threads = 8 warps in 4(M) x 2(N); warp tile 32x64; 128-row CTA tile.
__global__ void __launch_bounds__(256, 2)
k_gemm1(const float* __restrict__ x, const float* __restrict__ b1,
        const float* __restrict__ Wa, const float* __restrict__ ba, int N) {
    __shared__ float s_a[128];
    int tid = threadIdx.x, wid = tid >> 5, lane = tid & 31;
    int mw = wid & 3, nw = wid >> 2;
    int tig = lane & 3, g = lane >> 2;
    long row0 = (long)blockIdx.x * 128;

    if (tid < 128) s_a[tid] = 0.0f;
    __syncthreads();

    // per-lane A row pointers: rows row0 + mw*32 + mt*16 + rr*8 + g
    const float* xp[2][2];
    bool ok[2][2];
#pragma unroll
    for (int mt = 0; mt < 2; mt++)
#pragma unroll
        for (int rr = 0; rr < 2; rr++) {
            long r = row0 + mw * 32 + mt * 16 + rr * 8 + g;
            ok[mt][rr] = r < N;
            xp[mt][rr] = x + (ok[mt][rr] ? r : 0) * (long)IN_CH;
        }

    float acc[2][8][4];
#pragma unroll
    for (int a = 0; a < 2; a++)
#pragma unroll
        for (int b = 0; b < 8; b++)
#pragma unroll
            for (int q = 0; q < 4; q++) acc[a][b][q] = 0.0f;

    int bbase = nw * 4;   // first n16 block for this warp

#pragma unroll 1
    for (int t = 0; t < NT16; ++t) {
        int c0 = t * 16 + tig * 2;
        // ---- A loads (fp32, exactly the fragment elements) ----
        float2 v[2][2][2];
#pragma unroll
        for (int mt = 0; mt < 2; mt++)
#pragma unroll
            for (int rr = 0; rr < 2; rr++) {
                v[mt][rr][0] = ok[mt][rr] ? *(const float2*)(xp[mt][rr] + c0)
                                          : make_float2(0.f, 0.f);
                v[mt][rr][1] = ok[mt][rr] ? *(const float2*)(xp[mt][rr] + c0 + 8)
                                          : make_float2(0.f, 0.f);
            }
        // L2 prefetch next-next k16 line of x
        if (tig == 0 && t + 2 < NT16) {
#pragma unroll
            for (int mt = 0; mt < 2; mt++)
#pragma unroll
                for (int rr = 0; rr < 2; rr++)
                    if (ok[mt][rr])
                        asm volatile("prefetch.global.L2 [%0];"
                                     :: "l"(xp[mt][rr] + (t + 2) * 16));
        }
        // ---- split to bf16 hi/lo fragments in registers ----
        uint32_t ah[2][4], al[2][4];
#pragma unroll
        for (int mt = 0; mt < 2; mt++) {
            split2(v[mt][0][0], ah[mt][0], al[mt][0]);
            split2(v[mt][1][0], ah[mt][1], al[mt][1]);
            split2(v[mt][0][1], ah[mt][2], al[mt][2]);
            split2(v[mt][1][1], ah[mt][3], al[mt][3]);
        }
        // ---- B fragments via LDG (L2-hot table), JIT with 1-ahead ----
        size_t tb = ((size_t)t * 8 + bbase) * 32 + lane;
        uint4 bh = g_Wfh[tb], bl = g_Wfl[tb];
#pragma unroll
        for (int pp = 0; pp < 4; pp++) {
            uint4 nbh, nbl;
            if (pp < 3) { nbh = g_Wfh[tb + 32 * (pp + 1)]; nbl = g_Wfl[tb + 32 * (pp + 1)]; }
#pragma unroll
            for (int mt = 0; mt < 2; mt++) {
                MMA16816(acc[mt][2 * pp + 0], ah[mt][0], ah[mt][1], ah[mt][2], ah[mt][3], bh.x, bh.y);
                MMA16816(acc[mt][2 * pp + 1], ah[mt][0], ah[mt][1], ah[mt][2], ah[mt][3], bh.z, bh.w);
                MMA16816(acc[mt][2 * pp + 0], ah[mt][0], ah[mt][1], ah[mt][2], ah[mt][3], bl.x, bl.y);
                MMA16816(acc[mt][2 * pp + 1], ah[mt][0], ah[mt][1], ah[mt][2], ah[mt][3], bl.z, bl.w);
                MMA16816(acc[mt][2 * pp + 0], al[mt][0], al[mt][1], al[mt][2], al[mt][3], bh.x, bh.y);
                MMA16816(acc[mt][2 * pp + 1], al[mt][0], al[mt][1], al[mt][2], al[mt][3], bh.z, bh.w);
            }
            bh = nbh; bl = nbl;
        }
    }

    // ---- epilogue: bias + silu + logit + store h ----
    float2 b1v[8], wav[8];
#pragma unroll
    for (int nt = 0; nt < 8; nt++) {
        int cb = nw * 64 + nt * 8 + tig * 2;
        b1v[nt] = *(const float2*)&b1[cb];
        wav[nt] = *(const float2*)&Wa[cb];
    }
    long r0g = row0 + mw * 32 + g;
#pragma unroll
    for (int mt = 0; mt < 2; mt++) {
#pragma unroll
        for (int rh = 0; rh < 2; rh++) {
            long grow = r0g + mt * 16 + rh * 8;
            float part = 0.0f;
            if (grow < N) {
                float* hrow = g_h + (size_t)grow * HID;
#pragma unroll
                for (int nt = 0; nt < 8; nt++) {
                    float v0 = acc[mt][nt][rh * 2 + 0] + b1v[nt].x;
                    float v1 = acc[mt][nt][rh * 2 + 1] + b1v[nt].y;
                    float s0 = v0 / (1.0f + __expf(-v0));
                    float s1 = v1 / (1.0f + __expf(-v1));
                    part += s0 * wav[nt].x + s1 * wav[nt].y;
                    int cb = nw * 64 + nt * 8 + tig * 2;
                    *(float2*)(hrow + cb) = make_float2(s0, s1);
                }
            }
            part += __shfl_xor_sync(0xffffffffu, part, 1);
            part += __shfl_xor_sync(0xffffffffu, part, 2);
            if (tig == 0 && grow < N)
                atomicAdd(&s_a[(int)(grow - row0)], part);
        }
    }
    __syncthreads();
    if (tid < 128) {
        long row = row0 + tid;
        if (row < N) g_a[row] = s_a[tid] + ba[0];
    }
}

// ---------------- kernel: segment max ----------------
#define CHUNK 16
__global__ void k_segmax(const int* __restrict__ idx, int N) {
    int t = blockIdx.x * blockDim.x + threadIdx.x;
    int start = t * CHUNK;
    if (start >= N) return;
    int end = min(start + CHUNK, N);
    int cur = idx[start];
    float mx = g_a[start];
    for (int i = start + 1; i < end; i++) {
        int s = idx[i];
        float v = g_a[i];
        if (s == cur) mx = fmaxf(mx, v);
        else { atomicMax(&g_smax[cur], mapf(mx)); cur = s; mx = v; }
    }
    atomicMax(&g_smax[cur], mapf(mx));
}

// ---------------- kernel: exp + denom ----------------
__global__ void k_exp(const int* __restrict__ idx, int N) {
    int t = blockIdx.x * blockDim.x + threadIdx.x;
    int start = t * CHUNK;
    if (start >= N) return;
    int end = min(start + CHUNK, N);
    int cur = idx[start];
    float m = unmapf(g_smax[cur]);
    float ex = __expf(g_a[start] - m);
    g_e[start] = ex;
    float sum = ex;
    for (int i = start + 1; i < end; i++) {
        int s = idx[i];
        if (s != cur) {
            atomicAdd(&g_denom[cur], sum);
            cur = s; m = unmapf(g_smax[cur]); sum = 0.0f;
        }
        float e2 = __expf(g_a[i] - m);
        g_e[i] = e2;
        sum += e2;
    }
    atomicAdd(&g_denom[cur], sum);
}

// ---------------- kernel: weighted pooling over sorted runs ----------------
__global__ void __launch_bounds__(128)
k_pool(const int* __restrict__ idx, int N) {
    __shared__ int s_idx[256];
    __shared__ float s_w[256];
    int base = blockIdx.x * 256;
    int tid = threadIdx.x;
    for (int r = tid; r < 256; r += 128) {
        int row = base + r;
        if (row < N) {
            int sg = idx[row];
            s_idx[r] = sg;
            s_w[r] = g_e[row] / g_denom[sg];
        } else {
            s_idx[r] = -1;
        }
    }
    __syncthreads();

    int j = tid;
    float sum = 0.0f;
    int cur = s_idx[0];
#pragma unroll 1
    for (int rb = 0; rb < 256; rb += 8) {
        float hv[8];
#pragma unroll
        for (int u = 0; u < 8; u++)
            hv[u] = (s_idx[rb + u] >= 0)
                        ? g_h[(size_t)(base + rb + u) * HID + j] : 0.0f;
#pragma unroll
        for (int u = 0; u < 8; u++) {
            int sg = s_idx[rb + u];
            if (sg < 0) goto done;
            if (sg != cur) {
                atomicAdd(&g_pooled[(size_t)cur * HID + j], sum);
                sum = 0.0f; cur = sg;
            }
            sum += s_w[rb + u] * hv[u];
        }
    }
done:
    atomicAdd(&g_pooled[(size_t)cur * HID + j], sum);
}

// ---------------- kernel: out = pooled @ Wo + bo ----------------
__global__ void __launch_bounds__(256)
k_out(const float* __restrict__ Wo, const float* __restrict__ bo,
      float* __restrict__ out, int S) {
    __shared__ __align__(16) float Ps[64][HID];
    int tid = threadIdx.x;
    int row0 = blockIdx.x * 64;
#pragma unroll
    for (int i = 0; i < 8; i++) {
        int id = tid + i * 256;
        int r = id >> 5, c4 = id & 31;
        float4 v = make_float4(0.f, 0.f, 0.f, 0.f);
        if (row0 + r < S)
            v = *(const float4*)&g_pooled[(size_t)(row0 + r) * HID + c4 * 4];
        *(float4*)&Ps[r][c4 * 4] = v;
    }
    __syncthreads();

    int m_base = (tid >> 5) * 8;
    int n_base = (tid & 31) * 4;
    unsigned long long acc[8][2] = {};
#pragma unroll 4
    for (int k = 0; k < HID; k++) {
        float4 b = *(const float4*)&Wo[(size_t)k * OUT_CH + n_base];
        unsigned long long b0 = pk(b.x, b.y), b1p = pk(b.z, b.w);
#pragma unroll
        for (int mi = 0; mi < 8; mi++) {
            float av = Ps[m_base + mi][k];
            unsigned long long ad = pk(av, av);
            ffma2(acc[mi][0], ad, b0);
            ffma2(acc[mi][1], ad, b1p);
        }
    }
    float c0 = bo[n_base], c1 = bo[n_base + 1], c2 = bo[n_base + 2], c3 = bo[n_base + 3];
#pragma unroll
    for (int mi = 0; mi < 8; mi++) {
        int row = row0 + m_base + mi;
        if (row < S) {
            float l0, h0, l1, h1;
            unpk(acc[mi][0], l0, h0);
            unpk(acc[mi][1], l1, h1);
            *(float4*)&out[(size_t)row * OUT_CH + n_base] =
                make_float4(l0 + c0, h0 + c1, l1 + c2, h1 + c3);
        }
    }
}

// ---------------- launch ----------------
extern "C" void kernel_launch(void* const* d_in, const int* in_sizes, int n_in,
                              void* d_out, int out_size) {
    const float* x     = (const float*)d_in[0];
    const int*   index = (const int*)d_in[1];
    const float* W1 = (const float*)d_in[n_in - 6];
    const float* b1 = (const float*)d_in[n_in - 5];
    const float* Wa = (const float*)d_in[n_in - 4];
    const float* ba = (const float*)d_in[n_in - 3];
    const float* Wo = (const float*)d_in[n_in - 2];
    const float* bo = (const float*)d_in[n_in - 1];
    float* out = (float*)d_out;

    int N = in_sizes[0] / IN_CH;       // 1,000,000
    int S = out_size / OUT_CH;         // 50,000

    k_prepw<<<(NT16 * 8 * 32 + 255) / 256, 256>>>(W1);
    k_init<<<256, 256>>>(S);
    k_gemm1<<<(N + 127) / 128, 256>>>(x, b1, Wa, ba, N);
    int ct = (N + CHUNK - 1) / CHUNK;
    k_segmax<<<(ct + 255) / 256, 256>>>(index, N);
    k_exp<<<(ct + 255) / 256, 256>>>(index, N);
    k_pool<<<(N + 255) / 256, 128>>>(index, N);
    k_out<<<(S + 63) / 64, 256>>>(Wo, bo, out, S);
}